// round 13
// baseline (speedup 1.0000x reference)
#include <cuda_runtime.h>
#include <cuda_bf16.h>
#include <cuda_fp16.h>
#include <math.h>

#define H_   16
#define KV_  8
#define D_   128
#define HID_ 2048
#define Q_   1024
#define S_   8192
#define K2_  4096

// ---------------- device-global scratch ----------------
__device__ float  g_qkv[4096 * Q_];            // fused QKV projection [4096][1024] fp32
__device__ __half g_qh [H_*Q_*D_];             // fp16 Q, RoPE'd, scaled
__device__ __half g_khf[KV_*S_*D_];            // fp16 merged K (cache + new)
__device__ __half g_vhf[KV_*S_*D_];            // fp16 merged V
__device__ __half g_Wqkv[(size_t)4096*K2_];    // A-pack [ah|al] of 64*W
__device__ __half g_WoPk[(size_t)HID_*K2_];
__device__ __half g_hidT[(size_t)Q_*K2_];      // B-pack [bh|bh]
__device__ __half g_attnT[(size_t)Q_*K2_];     // B-pack [bh|bh]

// ---------------- PTX helpers ----------------
__device__ __forceinline__ void ldsm4(unsigned &r0,unsigned &r1,unsigned &r2,unsigned &r3,unsigned a){
    asm volatile("ldmatrix.sync.aligned.m8n8.x4.shared.b16 {%0,%1,%2,%3},[%4];"
                 :"=r"(r0),"=r"(r1),"=r"(r2),"=r"(r3):"r"(a));
}
__device__ __forceinline__ void ldsm4t(unsigned &r0,unsigned &r1,unsigned &r2,unsigned &r3,unsigned a){
    asm volatile("ldmatrix.sync.aligned.m8n8.x4.trans.shared.b16 {%0,%1,%2,%3},[%4];"
                 :"=r"(r0),"=r"(r1),"=r"(r2),"=r"(r3):"r"(a));
}
__device__ __forceinline__ void mma_f16(float c[4], const unsigned a[4], unsigned b0, unsigned b1){
    asm volatile("mma.sync.aligned.m16n8k16.row.col.f32.f16.f16.f32 "
                 "{%0,%1,%2,%3},{%4,%5,%6,%7},{%8,%9},{%0,%1,%2,%3};"
                 :"+f"(c[0]),"+f"(c[1]),"+f"(c[2]),"+f"(c[3])
                 :"r"(a[0]),"r"(a[1]),"r"(a[2]),"r"(a[3]),"r"(b0),"r"(b1));
}
__device__ __forceinline__ void cpa16(unsigned s, const void* g){
    asm volatile("cp.async.cg.shared.global [%0],[%1],16;"::"r"(s),"l"(g));
}
#define CPC()  asm volatile("cp.async.commit_group;")
#define CPW0() asm volatile("cp.async.wait_group 0;")
#define CPW1() asm volatile("cp.async.wait_group 1;")

__device__ __forceinline__ unsigned f2h2(float x, float y){
    __half2 h = __floats2half2_rn(x,y); return *reinterpret_cast<unsigned*>(&h);
}
__device__ __forceinline__ void hilo2h(float x, float y, unsigned &hi, unsigned &lo){
    __half hx=__float2half_rn(x), hy=__float2half_rn(y);
    __half2 hp=__halves2half2(hx,hy); hi=*reinterpret_cast<unsigned*>(&hp);
    __half lx=__float2half_rn(x-__half2float(hx));
    __half ly=__float2half_rn(y-__half2float(hy));
    __half2 lp=__halves2half2(lx,ly); lo=*reinterpret_cast<unsigned*>(&lp);
}

// ---------------- prep: ALL weight A-packs in one launch ----------------
// float4 regions: Wq [0,1048576), Wk [1048576,1572864), Wv [1572864,2097152),
// Wo [2097152,3145728). 3072 blocks x 256 thr x 4 float4; boundaries multiple of 1024.
__global__ __launch_bounds__(256)
void splitA_all_kernel(const float* __restrict__ Wq, const float* __restrict__ Wk,
                       const float* __restrict__ Wv, const float* __restrict__ Wo,
                       __half* __restrict__ qkvPk, __half* __restrict__ woPk){
    const size_t base = (size_t)blockIdx.x * 1024;
    const int t = threadIdx.x;
#pragma unroll
    for (int j=0;j<4;j++){
        size_t f = base + j*256 + t;
        const float* src; __half* dst; size_t local;
        if (f < 1048576u)      { src=Wq; dst=qkvPk;                  local=f; }
        else if (f < 1572864u) { src=Wk; dst=qkvPk+(size_t)2048*K2_; local=f-1048576u; }
        else if (f < 2097152u) { src=Wv; dst=qkvPk+(size_t)3072*K2_; local=f-1572864u; }
        else                   { src=Wo; dst=woPk;                   local=f-2097152u; }
        size_t lin = local*4;
        int col = (int)(lin & (HID_-1));
        size_t row = lin >> 11;
        float4 w = *(const float4*)(src + lin);
        unsigned h0,l0,h1,l1;
        hilo2h(w.x*64.f, w.y*64.f, h0, l0);
        hilo2h(w.z*64.f, w.w*64.f, h1, l1);
        size_t b = row*K2_ + col;
        *(uint2*)(dst+b)      = make_uint2(h0,h1);
        *(uint2*)(dst+b+HID_) = make_uint2(l0,l1);
    }
}

// ---------------- prep: hidden [2048][1024] -> hidT B-pack [bh|bh] ----------------
__global__ __launch_bounds__(256)
void transpose_splitB_kernel(const float* __restrict__ src, __half* __restrict__ dst){
    __shared__ float t[32][33];
    const int tx=threadIdx.x, ty=threadIdx.y;          // 32 x 8
    const int n0=blockIdx.x*32, k0=blockIdx.y*32;
#pragma unroll
    for (int r=0;r<4;r++)
        t[ty+8*r][tx] = src[(size_t)(k0+ty+8*r)*Q_ + n0+tx];
    __syncthreads();
#pragma unroll
    for (int r=0;r<4;r++){
        int n = ty+8*r;
        __half hb = __float2half_rn(t[tx][n]);
        size_t b = (size_t)(n0+n)*K2_ + k0+tx;
        dst[b]=hb; dst[b+HID_]=hb;
    }
}

// ---------------- packed-K fp16 GEMM, occupancy-optimized ----------------
// C[M][1024] = (A/64)[M][4096]*B[1024][4096]^T (+bias). CTA tile 128x64, 8 warps
// of 32x32, k-step 32, 2-stage static smem, 3 CTAs/SM (acc = 32 regs/thread).
__global__ __launch_bounds__(256, 3)
void gemm_pk_kernel(const __half* __restrict__ A, const __half* __restrict__ B,
                    const float* __restrict__ b0, const float* __restrict__ b1,
                    const float* __restrict__ b2, float* __restrict__ C){
    __shared__ __half sA[2][128*40];
    __shared__ __half sB[2][64*40];
    const int tid=threadIdx.x, lane=tid&31, warp=tid>>5;
    const int wm = warp>>1, wn = warp&1;               // 4 x 2 warp grid
    const int m0 = blockIdx.y*128, n0 = blockIdx.x*64;
    const unsigned uA=(unsigned)__cvta_generic_to_shared(&sA[0][0]);
    const unsigned uB=(unsigned)__cvta_generic_to_shared(&sB[0][0]);

    float acc[2][4][4];
#pragma unroll
    for (int a=0;a<2;a++)
#pragma unroll
        for (int b=0;b<4;b++)
#pragma unroll
            for (int c=0;c<4;c++) acc[a][b][c]=0.f;

    auto load=[&](int st,int k0){
#pragma unroll
        for (int i=0;i<2;i++){            // A: 512 chunks
            int c = tid + i*256;
            int row = c>>2, seg = c&3;
            cpa16(uA + (st*5120 + row*40 + seg*8)*2, A + (size_t)(m0+row)*K2_ + k0 + seg*8);
        }
        {                                  // B: 256 chunks
            int row = tid>>2, seg = tid&3;
            cpa16(uB + (st*2560 + row*40 + seg*8)*2, B + (size_t)(n0+row)*K2_ + k0 + seg*8);
        }
    };
    load(0,0); CPC();

    for (int kt=0;kt<128;kt++){
        int st = kt&1;
        if (kt<127){ load(st^1,(kt+1)*32); CPC(); CPW1(); } else { CPW0(); }
        __syncthreads();
#pragma unroll
        for (int kh=0;kh<2;kh++){
            unsigned a0[4], a1[4];
            unsigned ao = (unsigned)((st*5120 + (wm*32+(lane&15))*40 + kh*16 + (lane>>4)*8)*2);
            ldsm4(a0[0],a0[1],a0[2],a0[3], uA+ao);
            ldsm4(a1[0],a1[1],a1[2],a1[3], uA+ao + 16*40*2);
            unsigned bf_[4][2];
#pragma unroll
            for (int nt=0;nt<2;nt++){
                unsigned bo = (unsigned)((st*2560 + (wn*32+nt*16+(lane&15))*40 + kh*16 + (lane>>4)*8)*2);
                unsigned r0,r1,r2,r3;
                ldsm4(r0,r1,r2,r3, uB+bo);
                bf_[2*nt][0]=r0; bf_[2*nt][1]=r2; bf_[2*nt+1][0]=r1; bf_[2*nt+1][1]=r3;
            }
#pragma unroll
            for (int nf=0;nf<4;nf++){
                mma_f16(acc[0][nf], a0, bf_[nf][0], bf_[nf][1]);
                mma_f16(acc[1][nf], a1, bf_[nf][0], bf_[nf][1]);
            }
        }
        __syncthreads();
    }
    const float SC = 0.015625f;   // 1/64
#pragma unroll
    for (int mf=0;mf<2;mf++)
#pragma unroll
        for (int nf=0;nf<4;nf++){
            int row = m0 + wm*32 + mf*16 + (lane>>2);
            int col = n0 + wn*32 + nf*8 + (lane&3)*2;
            float bva = 0.f, bvb = 0.f;
            if (b0){
                int r2 = row + 8;
                bva = (row<2048)? b0[row] : ((row<3072)? b1[row-2048] : b2[row-3072]);
                bvb = (r2 <2048)? b0[r2]  : ((r2 <3072)? b1[r2 -2048] : b2[r2 -3072]);
            }
            C[(size_t)row*Q_ + col]       = acc[mf][nf][0]*SC + bva;
            C[(size_t)row*Q_ + col + 1]   = acc[mf][nf][1]*SC + bva;
            C[(size_t)(row+8)*Q_ + col]   = acc[mf][nf][2]*SC + bvb;
            C[(size_t)(row+8)*Q_ + col+1] = acc[mf][nf][3]*SC + bvb;
        }
}

// ---------------- fused RoPE: Q->g_qh, K/V new tokens -> cache slots (fp16) ----------------
__global__ __launch_bounds__(256)
void rope_all_kernel(const float* __restrict__ qkv, const float* __restrict__ cosQD,
                     const float* __restrict__ sinQD, const int* __restrict__ cposp,
                     __half* __restrict__ qh, __half* __restrict__ khf,
                     __half* __restrict__ vhf){
    __shared__ float tile[128][33];
    const int tx=threadIdx.x, ty=threadIdx.y;          // 32 x 8
    const int i0=blockIdx.x*32, slot=blockIdx.y;
    const int cpos = cposp[0];

    int srcrow; __half* dst; size_t drow0; int do_rope; float scale;
    if (slot < 16){ srcrow = slot*128;            dst=qh;  drow0=(size_t)slot*Q_ + i0;        do_rope=1; scale=0.08838834764831845f; }
    else if (slot < 24){ int kv=slot-16; srcrow = 2048 + kv*128; dst=khf; drow0=(size_t)kv*S_ + cpos + i0; do_rope=1; scale=1.f; }
    else { int kv=slot-24; srcrow = 3072 + kv*128; dst=vhf; drow0=(size_t)kv*S_ + cpos + i0; do_rope=0; scale=1.f; }

#pragma unroll
    for (int r=0;r<16;r++)
        tile[r*8+ty][tx] = qkv[(size_t)(srcrow + r*8+ty)*Q_ + i0+tx];
    __syncthreads();
    const int t = ty*32+tx;
#pragma unroll
    for (int r=0;r<16;r++){
        int idx = r*256 + t;
        int d = idx & 127, i = idx >> 7;
        float v = tile[d][i], outv;
        if (do_rope){
            float o = (d<64) ? -tile[d+64][i] : tile[d-64][i];
            outv = (v*cosQD[(size_t)(i0+i)*128+d] + o*sinQD[(size_t)(i0+i)*128+d])*scale;
        } else outv = v;
        dst[(drow0 + i)*128 + d] = __float2half_rn(outv);
    }
}

// ---------------- cache-only fp16 conversion (skips [cpos, cpos+Q)) ----------------
__global__ __launch_bounds__(256)
void merge_cache_kernel(const float* __restrict__ kc_, const float* __restrict__ vc_,
                        const int* __restrict__ cposp,
                        __half* __restrict__ khf, __half* __restrict__ vhf){
    const int cpos = cposp[0];
    const size_t base = (size_t)blockIdx.x * 512;
#pragma unroll
    for (int j=0;j<2;j++){
        size_t idx = base + j*256 + threadIdx.x;
        size_t lin = idx*4;
        int s = (int)((lin>>7) & (S_-1));
        if (s >= cpos && s < cpos + Q_) continue;
        float4 k4 = *(const float4*)(kc_+lin);
        float4 v4 = *(const float4*)(vc_+lin);
        *(uint2*)(khf+lin) = make_uint2(f2h2(k4.x,k4.y), f2h2(k4.z,k4.w));
        *(uint2*)(vhf+lin) = make_uint2(f2h2(v4.x,v4.y), f2h2(v4.z,v4.w));
    }
}

// ---------------- flash attention, fp16 MMA, double-buffered K/V ----------------
__global__ __launch_bounds__(128)
void attn_kernel(const __half* __restrict__ qh, const __half* __restrict__ khf,
                 const __half* __restrict__ vhf, const int* __restrict__ cposp,
                 __half* __restrict__ attnT){
    extern __shared__ __half smh[];
    const int TS = 64*136;
    const int tid=threadIdx.x, lane=tid&31, w=tid>>5;
    const int q0=blockIdx.x*64, h=blockIdx.y, kv=h>>1;
    const int cpos = cposp[0];
    const unsigned sb=(unsigned)__cvta_generic_to_shared(smh);
    const unsigned uQ=sb;
    const unsigned uKb[2] = { sb+TS*2,   sb+3*TS*2 };
    const unsigned uVb[2] = { sb+2*TS*2, sb+4*TS*2 };

#pragma unroll
    for (int i=0;i<8;i++){
        int c = tid + i*128;
        int row = c>>4, seg = c&15;
        cpa16(uQ + (unsigned)((row*136 + seg*8)*2),
              qh + ((size_t)h*Q_ + q0 + row)*128 + seg*8);
    }
    CPC();

    auto ldkv = [&](int sbk, int buf){
        int s0 = sbk*64;
#pragma unroll
        for (int i=0;i<8;i++){
            int c = tid + i*128;
            int row = c>>4, seg = c&15;
            size_t gk = ((size_t)kv*S_ + s0 + row)*128 + seg*8;
            unsigned so = (unsigned)((row*136 + seg*8)*2);
            cpa16(uKb[buf]+so, khf+gk);
            cpa16(uVb[buf]+so, vhf+gk);
        }
        CPC();
    };

    float out[16][4];
#pragma unroll
    for (int a=0;a<16;a++)
#pragma unroll
        for (int c=0;c<4;c++) out[a][c]=0.f;
    float m0=-1e30f, m1=-1e30f, l0=0.f, l1=0.f;
    const int r0 = lane>>2, qb = q0 + w*16;

    int nblk = (cpos + q0 + 63)/64 + 1;
    if (nblk > S_/64) nblk = S_/64;

    ldkv(0,0);

    for (int sbk=0; sbk<nblk; sbk++){
        const int s0 = sbk*64;
        const int b = sbk&1;
        if (sbk+1 < nblk){ ldkv(sbk+1, b^1); CPW1(); } else { CPW0(); }
        __syncthreads();
        const unsigned uK = uKb[b], uV = uVb[b];

        float sc[8][4];
#pragma unroll
        for (int a=0;a<8;a++)
#pragma unroll
            for (int c=0;c<4;c++) sc[a][c]=0.f;
#pragma unroll
        for (int kd=0;kd<8;kd++){
            unsigned aq[4];
            unsigned qo = (unsigned)(((w*16+(lane&15))*136 + kd*16 + (lane>>4)*8)*2);
            ldsm4(aq[0],aq[1],aq[2],aq[3], uQ+qo);
#pragma unroll
            for (int nt=0;nt<4;nt++){
                unsigned ko = (unsigned)(((nt*16+(lane&15))*136 + kd*16 + (lane>>4)*8)*2);
                unsigned k0r,k1r,k2r,k3r;
                ldsm4(k0r,k1r,k2r,k3r, uK+ko);
                mma_f16(sc[2*nt],   aq, k0r,k2r);
                mma_f16(sc[2*nt+1], aq, k1r,k3r);
            }
        }

        if (s0 + 63 > cpos + qb){
            int lim0 = cpos + qb + r0, lim1 = lim0 + 8;
#pragma unroll
            for (int nf=0;nf<8;nf++){
                int j = s0 + nf*8 + 2*(lane&3);
                if (j   > lim0) sc[nf][0] = -1e30f;
                if (j+1 > lim0) sc[nf][1] = -1e30f;
                if (j   > lim1) sc[nf][2] = -1e30f;
                if (j+1 > lim1) sc[nf][3] = -1e30f;
            }
        }

        float mx0=-1e30f, mx1=-1e30f;
#pragma unroll
        for (int nf=0;nf<8;nf++){
            mx0 = fmaxf(mx0, fmaxf(sc[nf][0], sc[nf][1]));
            mx1 = fmaxf(mx1, fmaxf(sc[nf][2], sc[nf][3]));
        }
        mx0 = fmaxf(mx0, __shfl_xor_sync(0xffffffffu, mx0, 1));
        mx0 = fmaxf(mx0, __shfl_xor_sync(0xffffffffu, mx0, 2));
        mx1 = fmaxf(mx1, __shfl_xor_sync(0xffffffffu, mx1, 1));
        mx1 = fmaxf(mx1, __shfl_xor_sync(0xffffffffu, mx1, 2));
        float n0_ = fmaxf(m0, mx0), n1_ = fmaxf(m1, mx1);
        float s0f = __expf(m0 - n0_), s1f = __expf(m1 - n1_);
        m0 = n0_; m1 = n1_;
        float ps0=0.f, ps1=0.f;
#pragma unroll
        for (int nf=0;nf<8;nf++){
            sc[nf][0]=__expf(sc[nf][0]-m0); ps0+=sc[nf][0];
            sc[nf][1]=__expf(sc[nf][1]-m0); ps0+=sc[nf][1];
            sc[nf][2]=__expf(sc[nf][2]-m1); ps1+=sc[nf][2];
            sc[nf][3]=__expf(sc[nf][3]-m1); ps1+=sc[nf][3];
        }
        ps0 += __shfl_xor_sync(0xffffffffu, ps0, 1);
        ps0 += __shfl_xor_sync(0xffffffffu, ps0, 2);
        ps1 += __shfl_xor_sync(0xffffffffu, ps1, 1);
        ps1 += __shfl_xor_sync(0xffffffffu, ps1, 2);
        l0 = l0*s0f + ps0;
        l1 = l1*s1f + ps1;
#pragma unroll
        for (int df=0;df<16;df++){
            out[df][0]*=s0f; out[df][1]*=s0f; out[df][2]*=s1f; out[df][3]*=s1f;
        }

#pragma unroll
        for (int kc=0;kc<4;kc++){
            unsigned ph[4];
            ph[0] = f2h2(sc[2*kc][0],   sc[2*kc][1]);
            ph[1] = f2h2(sc[2*kc][2],   sc[2*kc][3]);
            ph[2] = f2h2(sc[2*kc+1][0], sc[2*kc+1][1]);
            ph[3] = f2h2(sc[2*kc+1][2], sc[2*kc+1][3]);
#pragma unroll
            for (int dt=0;dt<8;dt++){
                unsigned vo = (unsigned)(((kc*16+(lane&15))*136 + dt*16 + (lane>>4)*8)*2);
                unsigned v0,v1,v2,v3;
                ldsm4t(v0,v1,v2,v3, uV+vo);
                mma_f16(out[2*dt],   ph, v0,v1);
                mma_f16(out[2*dt+1], ph, v2,v3);
            }
        }
        __syncthreads();
    }

    float inv0 = 1.f/l0, inv1 = 1.f/l1;
    int qrow0 = qb + r0, qrow1 = qrow0 + 8;
#pragma unroll
    for (int df=0;df<16;df++){
        int colg = h*128 + df*8 + (lane&3)*2;
        unsigned hv;
        hv = f2h2(out[df][0]*inv0, out[df][1]*inv0);
        *(unsigned*)(attnT + (size_t)qrow0*K2_ + colg)        = hv;
        *(unsigned*)(attnT + (size_t)qrow0*K2_ + 2048 + colg) = hv;
        hv = f2h2(out[df][2]*inv1, out[df][3]*inv1);
        *(unsigned*)(attnT + (size_t)qrow1*K2_ + colg)        = hv;
        *(unsigned*)(attnT + (size_t)qrow1*K2_ + 2048 + colg) = hv;
    }
}

// ---------------- launch ----------------
extern "C" void kernel_launch(void* const* d_in, const int* in_sizes, int n_in,
                              void* d_out, int out_size){
    const float* hidden = (const float*)d_in[0];
    const float* cosQD  = (const float*)d_in[1];
    const float* sinQD  = (const float*)d_in[2];
    const float* kcache = (const float*)d_in[6];
    const float* vcache = (const float*)d_in[7];
    const float* Wq = (const float*)d_in[8];
    const float* bq = (const float*)d_in[9];
    const float* Wk = (const float*)d_in[10];
    const float* bk = (const float*)d_in[11];
    const float* Wv = (const float*)d_in[12];
    const float* bv = (const float*)d_in[13];
    const float* Wo = (const float*)d_in[14];
    const int* cpos = (const int*)d_in[15];
    float* out = (float*)d_out;

    float *pqkv;
    __half *pqh,*pkhf,*pvhf,*pWqkv,*pWo,*pHid,*pAtt;
    cudaGetSymbolAddress((void**)&pqkv,g_qkv);
    cudaGetSymbolAddress((void**)&pqh,g_qh);
    cudaGetSymbolAddress((void**)&pkhf,g_khf);  cudaGetSymbolAddress((void**)&pvhf,g_vhf);
    cudaGetSymbolAddress((void**)&pWqkv,g_Wqkv);cudaGetSymbolAddress((void**)&pWo,g_WoPk);
    cudaGetSymbolAddress((void**)&pHid,g_hidT); cudaGetSymbolAddress((void**)&pAtt,g_attnT);

    // cache-only fp16 conversion (independent; runs first)
    merge_cache_kernel<<<(KV_*S_*D_/4)/512, 256>>>(kcache, vcache, cpos, pkhf, pvhf);

    // all weight packs in one launch
    splitA_all_kernel<<<3072, 256>>>(Wq, Wk, Wv, Wo, pWqkv, pWo);
    transpose_splitB_kernel<<<dim3(Q_/32, HID_/32), dim3(32,8)>>>(hidden, pHid);

    // fused QKV projection (M=4096) on fp16 HMMA, 128x64 tiles, 3 CTAs/SM
    gemm_pk_kernel<<<dim3(Q_/64, 32), 256>>>(pWqkv, pHid, bq, bk, bv, pqkv);

    // fused RoPE: Q -> g_qh (fp16, scaled); K/V new tokens -> cache slots (fp16)
    rope_all_kernel<<<dim3(Q_/32, 32), dim3(32,8)>>>(pqkv, cosQD, sinQD, cpos, pqh, pkhf, pvhf);

    // flash attention (fp16, double-buffered K/V)
    const int ATTN_SMEM = 5*64*136*2;   // 87040 B
    cudaFuncSetAttribute(attn_kernel, cudaFuncAttributeMaxDynamicSharedMemorySize, ATTN_SMEM);
    attn_kernel<<<dim3(Q_/64, H_), 128, ATTN_SMEM>>>(pqh, pkhf, pvhf, cpos, pAtt);

    // output projection on fp16 HMMA (no bias)
    gemm_pk_kernel<<<dim3(Q_/64, 16), 256>>>(pWo, pAtt, nullptr, nullptr, nullptr, out);
}

// round 14
// speedup vs baseline: 1.0646x; 1.0646x over previous
#include <cuda_runtime.h>
#include <cuda_bf16.h>
#include <cuda_fp16.h>
#include <math.h>

#define H_   16
#define KV_  8
#define D_   128
#define HID_ 2048
#define Q_   1024
#define S_   8192
#define K2_  4096

// ---------------- device-global scratch ----------------
__device__ float  g_qkv[4096 * Q_];            // fused QKV projection [4096][1024] fp32
__device__ __half g_qh [H_*Q_*D_];             // fp16 Q, RoPE'd, scaled
__device__ __half g_khf[KV_*S_*D_];            // fp16 merged K (cache + new)
__device__ __half g_vhf[KV_*S_*D_];            // fp16 merged V
__device__ __half g_Wqkv[(size_t)4096*K2_];    // A-pack [ah|al] of 64*W
__device__ __half g_WoPk[(size_t)HID_*K2_];
__device__ __half g_hidT[(size_t)Q_*K2_];      // B-pack [bh|bh]
__device__ __half g_attnT[(size_t)Q_*K2_];     // B-pack [bh|bh]

// ---------------- PTX helpers ----------------
__device__ __forceinline__ void ldsm4(unsigned &r0,unsigned &r1,unsigned &r2,unsigned &r3,unsigned a){
    asm volatile("ldmatrix.sync.aligned.m8n8.x4.shared.b16 {%0,%1,%2,%3},[%4];"
                 :"=r"(r0),"=r"(r1),"=r"(r2),"=r"(r3):"r"(a));
}
__device__ __forceinline__ void ldsm4t(unsigned &r0,unsigned &r1,unsigned &r2,unsigned &r3,unsigned a){
    asm volatile("ldmatrix.sync.aligned.m8n8.x4.trans.shared.b16 {%0,%1,%2,%3},[%4];"
                 :"=r"(r0),"=r"(r1),"=r"(r2),"=r"(r3):"r"(a));
}
__device__ __forceinline__ void mma_f16(float c[4], const unsigned a[4], unsigned b0, unsigned b1){
    asm volatile("mma.sync.aligned.m16n8k16.row.col.f32.f16.f16.f32 "
                 "{%0,%1,%2,%3},{%4,%5,%6,%7},{%8,%9},{%0,%1,%2,%3};"
                 :"+f"(c[0]),"+f"(c[1]),"+f"(c[2]),"+f"(c[3])
                 :"r"(a[0]),"r"(a[1]),"r"(a[2]),"r"(a[3]),"r"(b0),"r"(b1));
}
__device__ __forceinline__ void cpa16(unsigned s, const void* g){
    asm volatile("cp.async.cg.shared.global [%0],[%1],16;"::"r"(s),"l"(g));
}
#define CPC()  asm volatile("cp.async.commit_group;")
#define CPW0() asm volatile("cp.async.wait_group 0;")
#define CPW1() asm volatile("cp.async.wait_group 1;")

__device__ __forceinline__ unsigned f2h2(float x, float y){
    __half2 h = __floats2half2_rn(x,y); return *reinterpret_cast<unsigned*>(&h);
}
__device__ __forceinline__ void hilo2h(float x, float y, unsigned &hi, unsigned &lo){
    __half hx=__float2half_rn(x), hy=__float2half_rn(y);
    __half2 hp=__halves2half2(hx,hy); hi=*reinterpret_cast<unsigned*>(&hp);
    __half lx=__float2half_rn(x-__half2float(hx));
    __half ly=__float2half_rn(y-__half2float(hy));
    __half2 lp=__halves2half2(lx,ly); lo=*reinterpret_cast<unsigned*>(&lp);
}

// ---------------- prep: ALL weight A-packs in one launch ----------------
// float4 regions: Wq [0,1048576), Wk [1048576,1572864), Wv [1572864,2097152),
// Wo [2097152,3145728). 3072 blocks x 256 thr x 4 float4; boundaries multiple of 1024.
__global__ __launch_bounds__(256)
void splitA_all_kernel(const float* __restrict__ Wq, const float* __restrict__ Wk,
                       const float* __restrict__ Wv, const float* __restrict__ Wo,
                       __half* __restrict__ qkvPk, __half* __restrict__ woPk){
    const size_t base = (size_t)blockIdx.x * 1024;
    const int t = threadIdx.x;
#pragma unroll
    for (int j=0;j<4;j++){
        size_t f = base + j*256 + t;
        const float* src; __half* dst; size_t local;
        if (f < 1048576u)      { src=Wq; dst=qkvPk;                  local=f; }
        else if (f < 1572864u) { src=Wk; dst=qkvPk+(size_t)2048*K2_; local=f-1048576u; }
        else if (f < 2097152u) { src=Wv; dst=qkvPk+(size_t)3072*K2_; local=f-1572864u; }
        else                   { src=Wo; dst=woPk;                   local=f-2097152u; }
        size_t lin = local*4;
        int col = (int)(lin & (HID_-1));
        size_t row = lin >> 11;
        float4 w = *(const float4*)(src + lin);
        unsigned h0,l0,h1,l1;
        hilo2h(w.x*64.f, w.y*64.f, h0, l0);
        hilo2h(w.z*64.f, w.w*64.f, h1, l1);
        size_t b = row*K2_ + col;
        *(uint2*)(dst+b)      = make_uint2(h0,h1);
        *(uint2*)(dst+b+HID_) = make_uint2(l0,l1);
    }
}

// ---------------- prep: hidden [2048][1024] -> hidT B-pack [bh|bh] ----------------
__global__ __launch_bounds__(256)
void transpose_splitB_kernel(const float* __restrict__ src, __half* __restrict__ dst){
    __shared__ float t[32][33];
    const int tx=threadIdx.x, ty=threadIdx.y;          // 32 x 8
    const int n0=blockIdx.x*32, k0=blockIdx.y*32;
#pragma unroll
    for (int r=0;r<4;r++)
        t[ty+8*r][tx] = src[(size_t)(k0+ty+8*r)*Q_ + n0+tx];
    __syncthreads();
#pragma unroll
    for (int r=0;r<4;r++){
        int n = ty+8*r;
        __half hb = __float2half_rn(t[tx][n]);
        size_t b = (size_t)(n0+n)*K2_ + k0+tx;
        dst[b]=hb; dst[b+HID_]=hb;
    }
}

// ---------------- packed-K fp16 GEMM (proven round-10 config) ----------------
// C[M][1024] = (A/64)[M][4096]*B[1024][4096]^T (+bias). 128x128 CTA tile, 8 warps
// of 32x64, k-step 32, 2-stage static smem, stride-40.
__global__ __launch_bounds__(256)
void gemm_pk_kernel(const __half* __restrict__ A, const __half* __restrict__ B,
                    const float* __restrict__ b0, const float* __restrict__ b1,
                    const float* __restrict__ b2, float* __restrict__ C){
    __shared__ __half sA[2][128*40];
    __shared__ __half sB[2][128*40];
    const int tid=threadIdx.x, lane=tid&31, warp=tid>>5;
    const int wm = warp>>1, wn = warp&1;
    const int m0 = blockIdx.y*128, n0 = blockIdx.x*128;
    const unsigned uA=(unsigned)__cvta_generic_to_shared(&sA[0][0]);
    const unsigned uB=(unsigned)__cvta_generic_to_shared(&sB[0][0]);

    float acc[2][8][4];
#pragma unroll
    for (int a=0;a<2;a++)
#pragma unroll
        for (int b=0;b<8;b++)
#pragma unroll
            for (int c=0;c<4;c++) acc[a][b][c]=0.f;

    auto load=[&](int st,int k0){
#pragma unroll
        for (int i=0;i<2;i++){
            int c = tid + i*256;
            int row = c>>2, seg = c&3;
            cpa16(uA + (st*5120 + row*40 + seg*8)*2, A + (size_t)(m0+row)*K2_ + k0 + seg*8);
            cpa16(uB + (st*5120 + row*40 + seg*8)*2, B + (size_t)(n0+row)*K2_ + k0 + seg*8);
        }
    };
    load(0,0); CPC();

    for (int kt=0;kt<128;kt++){
        int st = kt&1;
        if (kt<127){ load(st^1,(kt+1)*32); CPC(); CPW1(); } else { CPW0(); }
        __syncthreads();
#pragma unroll
        for (int kh=0;kh<2;kh++){
            unsigned a0[4], a1[4];
            unsigned ao = (unsigned)((st*5120 + (wm*32+(lane&15))*40 + kh*16 + (lane>>4)*8)*2);
            ldsm4(a0[0],a0[1],a0[2],a0[3], uA+ao);
            ldsm4(a1[0],a1[1],a1[2],a1[3], uA+ao + 16*40*2);
            unsigned bf_[8][2];
#pragma unroll
            for (int nt=0;nt<4;nt++){
                unsigned bo = (unsigned)((st*5120 + (wn*64+nt*16+(lane&15))*40 + kh*16 + (lane>>4)*8)*2);
                unsigned r0,r1,r2,r3;
                ldsm4(r0,r1,r2,r3, uB+bo);
                bf_[2*nt][0]=r0; bf_[2*nt][1]=r2; bf_[2*nt+1][0]=r1; bf_[2*nt+1][1]=r3;
            }
#pragma unroll
            for (int nf=0;nf<8;nf++){
                mma_f16(acc[0][nf], a0, bf_[nf][0], bf_[nf][1]);
                mma_f16(acc[1][nf], a1, bf_[nf][0], bf_[nf][1]);
            }
        }
        __syncthreads();
    }
    const float SC = 0.015625f;   // 1/64
#pragma unroll
    for (int mf=0;mf<2;mf++)
#pragma unroll
        for (int nf=0;nf<8;nf++){
            int row = m0 + wm*32 + mf*16 + (lane>>2);
            int col = n0 + wn*64 + nf*8 + (lane&3)*2;
            float bva = 0.f, bvb = 0.f;
            if (b0){
                int r2 = row + 8;
                bva = (row<2048)? b0[row] : ((row<3072)? b1[row-2048] : b2[row-3072]);
                bvb = (r2 <2048)? b0[r2]  : ((r2 <3072)? b1[r2 -2048] : b2[r2 -3072]);
            }
            C[(size_t)row*Q_ + col]       = acc[mf][nf][0]*SC + bva;
            C[(size_t)row*Q_ + col + 1]   = acc[mf][nf][1]*SC + bva;
            C[(size_t)(row+8)*Q_ + col]   = acc[mf][nf][2]*SC + bvb;
            C[(size_t)(row+8)*Q_ + col+1] = acc[mf][nf][3]*SC + bvb;
        }
}

// ---------------- fused RoPE: Q->g_qh, K/V new tokens -> cache slots (fp16) ----------------
// grid (Q_/32, 32): y<16 = q head; 16..23 = k (kv=y-16, RoPE); 24..31 = v (copy).
__global__ __launch_bounds__(256)
void rope_all_kernel(const float* __restrict__ qkv, const float* __restrict__ cosQD,
                     const float* __restrict__ sinQD, const int* __restrict__ cposp,
                     __half* __restrict__ qh, __half* __restrict__ khf,
                     __half* __restrict__ vhf){
    __shared__ float tile[128][33];
    const int tx=threadIdx.x, ty=threadIdx.y;          // 32 x 8
    const int i0=blockIdx.x*32, slot=blockIdx.y;
    const int cpos = cposp[0];

    int srcrow; __half* dst; size_t drow0; int do_rope; float scale;
    if (slot < 16){ srcrow = slot*128;            dst=qh;  drow0=(size_t)slot*Q_ + i0;        do_rope=1; scale=0.08838834764831845f; }
    else if (slot < 24){ int kv=slot-16; srcrow = 2048 + kv*128; dst=khf; drow0=(size_t)kv*S_ + cpos + i0; do_rope=1; scale=1.f; }
    else { int kv=slot-24; srcrow = 3072 + kv*128; dst=vhf; drow0=(size_t)kv*S_ + cpos + i0; do_rope=0; scale=1.f; }

#pragma unroll
    for (int r=0;r<16;r++)
        tile[r*8+ty][tx] = qkv[(size_t)(srcrow + r*8+ty)*Q_ + i0+tx];
    __syncthreads();
    const int t = ty*32+tx;
#pragma unroll
    for (int r=0;r<16;r++){
        int idx = r*256 + t;
        int d = idx & 127, i = idx >> 7;
        float v = tile[d][i], outv;
        if (do_rope){
            float o = (d<64) ? -tile[d+64][i] : tile[d-64][i];
            outv = (v*cosQD[(size_t)(i0+i)*128+d] + o*sinQD[(size_t)(i0+i)*128+d])*scale;
        } else outv = v;
        dst[(drow0 + i)*128 + d] = __float2half_rn(outv);
    }
}

// ---------------- cache fp16 conversion — ONLY slots attention can read ----------------
// Attention reads keys s <= cpos+q0+63 < cpos+Q, and [cpos, cpos+Q) is written by
// rope_all. So everything s >= cpos is skipped here (37.5% less traffic).
__global__ __launch_bounds__(256)
void merge_cache_kernel(const float* __restrict__ kc_, const float* __restrict__ vc_,
                        const int* __restrict__ cposp,
                        __half* __restrict__ khf, __half* __restrict__ vhf){
    const int cpos = cposp[0];
    const size_t base = (size_t)blockIdx.x * 512;
#pragma unroll
    for (int j=0;j<2;j++){
        size_t idx = base + j*256 + threadIdx.x;
        size_t lin = idx*4;
        int s = (int)((lin>>7) & (S_-1));
        if (s >= cpos) continue;          // [cpos,cpos+Q) by rope_all; [cpos+Q,S) never read
        float4 k4 = *(const float4*)(kc_+lin);
        float4 v4 = *(const float4*)(vc_+lin);
        *(uint2*)(khf+lin) = make_uint2(f2h2(k4.x,k4.y), f2h2(k4.z,k4.w));
        *(uint2*)(vhf+lin) = make_uint2(f2h2(v4.x,v4.y), f2h2(v4.z,v4.w));
    }
}

// ---------------- flash attention, fp16 MMA, double-buffered K/V ----------------
__global__ __launch_bounds__(128)
void attn_kernel(const __half* __restrict__ qh, const __half* __restrict__ khf,
                 const __half* __restrict__ vhf, const int* __restrict__ cposp,
                 __half* __restrict__ attnT){
    extern __shared__ __half smh[];
    const int TS = 64*136;
    const int tid=threadIdx.x, lane=tid&31, w=tid>>5;
    const int q0=blockIdx.x*64, h=blockIdx.y, kv=h>>1;
    const int cpos = cposp[0];
    const unsigned sb=(unsigned)__cvta_generic_to_shared(smh);
    const unsigned uQ=sb;
    const unsigned uKb[2] = { sb+TS*2,   sb+3*TS*2 };
    const unsigned uVb[2] = { sb+2*TS*2, sb+4*TS*2 };

#pragma unroll
    for (int i=0;i<8;i++){
        int c = tid + i*128;
        int row = c>>4, seg = c&15;
        cpa16(uQ + (unsigned)((row*136 + seg*8)*2),
              qh + ((size_t)h*Q_ + q0 + row)*128 + seg*8);
    }
    CPC();

    auto ldkv = [&](int sbk, int buf){
        int s0 = sbk*64;
#pragma unroll
        for (int i=0;i<8;i++){
            int c = tid + i*128;
            int row = c>>4, seg = c&15;
            size_t gk = ((size_t)kv*S_ + s0 + row)*128 + seg*8;
            unsigned so = (unsigned)((row*136 + seg*8)*2);
            cpa16(uKb[buf]+so, khf+gk);
            cpa16(uVb[buf]+so, vhf+gk);
        }
        CPC();
    };

    float out[16][4];
#pragma unroll
    for (int a=0;a<16;a++)
#pragma unroll
        for (int c=0;c<4;c++) out[a][c]=0.f;
    float m0=-1e30f, m1=-1e30f, l0=0.f, l1=0.f;
    const int r0 = lane>>2, qb = q0 + w*16;

    int nblk = (cpos + q0 + 63)/64 + 1;
    if (nblk > S_/64) nblk = S_/64;

    ldkv(0,0);

    for (int sbk=0; sbk<nblk; sbk++){
        const int s0 = sbk*64;
        const int b = sbk&1;
        if (sbk+1 < nblk){ ldkv(sbk+1, b^1); CPW1(); } else { CPW0(); }
        __syncthreads();
        const unsigned uK = uKb[b], uV = uVb[b];

        float sc[8][4];
#pragma unroll
        for (int a=0;a<8;a++)
#pragma unroll
            for (int c=0;c<4;c++) sc[a][c]=0.f;
#pragma unroll
        for (int kd=0;kd<8;kd++){
            unsigned aq[4];
            unsigned qo = (unsigned)(((w*16+(lane&15))*136 + kd*16 + (lane>>4)*8)*2);
            ldsm4(aq[0],aq[1],aq[2],aq[3], uQ+qo);
#pragma unroll
            for (int nt=0;nt<4;nt++){
                unsigned ko = (unsigned)(((nt*16+(lane&15))*136 + kd*16 + (lane>>4)*8)*2);
                unsigned k0r,k1r,k2r,k3r;
                ldsm4(k0r,k1r,k2r,k3r, uK+ko);
                mma_f16(sc[2*nt],   aq, k0r,k2r);
                mma_f16(sc[2*nt+1], aq, k1r,k3r);
            }
        }

        if (s0 + 63 > cpos + qb){
            int lim0 = cpos + qb + r0, lim1 = lim0 + 8;
#pragma unroll
            for (int nf=0;nf<8;nf++){
                int j = s0 + nf*8 + 2*(lane&3);
                if (j   > lim0) sc[nf][0] = -1e30f;
                if (j+1 > lim0) sc[nf][1] = -1e30f;
                if (j   > lim1) sc[nf][2] = -1e30f;
                if (j+1 > lim1) sc[nf][3] = -1e30f;
            }
        }

        float mx0=-1e30f, mx1=-1e30f;
#pragma unroll
        for (int nf=0;nf<8;nf++){
            mx0 = fmaxf(mx0, fmaxf(sc[nf][0], sc[nf][1]));
            mx1 = fmaxf(mx1, fmaxf(sc[nf][2], sc[nf][3]));
        }
        mx0 = fmaxf(mx0, __shfl_xor_sync(0xffffffffu, mx0, 1));
        mx0 = fmaxf(mx0, __shfl_xor_sync(0xffffffffu, mx0, 2));
        mx1 = fmaxf(mx1, __shfl_xor_sync(0xffffffffu, mx1, 1));
        mx1 = fmaxf(mx1, __shfl_xor_sync(0xffffffffu, mx1, 2));
        float n0_ = fmaxf(m0, mx0), n1_ = fmaxf(m1, mx1);
        float s0f = __expf(m0 - n0_), s1f = __expf(m1 - n1_);
        m0 = n0_; m1 = n1_;
        float ps0=0.f, ps1=0.f;
#pragma unroll
        for (int nf=0;nf<8;nf++){
            sc[nf][0]=__expf(sc[nf][0]-m0); ps0+=sc[nf][0];
            sc[nf][1]=__expf(sc[nf][1]-m0); ps0+=sc[nf][1];
            sc[nf][2]=__expf(sc[nf][2]-m1); ps1+=sc[nf][2];
            sc[nf][3]=__expf(sc[nf][3]-m1); ps1+=sc[nf][3];
        }
        ps0 += __shfl_xor_sync(0xffffffffu, ps0, 1);
        ps0 += __shfl_xor_sync(0xffffffffu, ps0, 2);
        ps1 += __shfl_xor_sync(0xffffffffu, ps1, 1);
        ps1 += __shfl_xor_sync(0xffffffffu, ps1, 2);
        l0 = l0*s0f + ps0;
        l1 = l1*s1f + ps1;
#pragma unroll
        for (int df=0;df<16;df++){
            out[df][0]*=s0f; out[df][1]*=s0f; out[df][2]*=s1f; out[df][3]*=s1f;
        }

#pragma unroll
        for (int kc=0;kc<4;kc++){
            unsigned ph[4];
            ph[0] = f2h2(sc[2*kc][0],   sc[2*kc][1]);
            ph[1] = f2h2(sc[2*kc][2],   sc[2*kc][3]);
            ph[2] = f2h2(sc[2*kc+1][0], sc[2*kc+1][1]);
            ph[3] = f2h2(sc[2*kc+1][2], sc[2*kc+1][3]);
#pragma unroll
            for (int dt=0;dt<8;dt++){
                unsigned vo = (unsigned)(((kc*16+(lane&15))*136 + dt*16 + (lane>>4)*8)*2);
                unsigned v0,v1,v2,v3;
                ldsm4t(v0,v1,v2,v3, uV+vo);
                mma_f16(out[2*dt],   ph, v0,v1);
                mma_f16(out[2*dt+1], ph, v2,v3);
            }
        }
        __syncthreads();
    }

    float inv0 = 1.f/l0, inv1 = 1.f/l1;
    int qrow0 = qb + r0, qrow1 = qrow0 + 8;
#pragma unroll
    for (int df=0;df<16;df++){
        int colg = h*128 + df*8 + (lane&3)*2;
        unsigned hv;
        hv = f2h2(out[df][0]*inv0, out[df][1]*inv0);
        *(unsigned*)(attnT + (size_t)qrow0*K2_ + colg)        = hv;
        *(unsigned*)(attnT + (size_t)qrow0*K2_ + 2048 + colg) = hv;
        hv = f2h2(out[df][2]*inv1, out[df][3]*inv1);
        *(unsigned*)(attnT + (size_t)qrow1*K2_ + colg)        = hv;
        *(unsigned*)(attnT + (size_t)qrow1*K2_ + 2048 + colg) = hv;
    }
}

// ---------------- launch ----------------
extern "C" void kernel_launch(void* const* d_in, const int* in_sizes, int n_in,
                              void* d_out, int out_size){
    const float* hidden = (const float*)d_in[0];
    const float* cosQD  = (const float*)d_in[1];
    const float* sinQD  = (const float*)d_in[2];
    const float* kcache = (const float*)d_in[6];
    const float* vcache = (const float*)d_in[7];
    const float* Wq = (const float*)d_in[8];
    const float* bq = (const float*)d_in[9];
    const float* Wk = (const float*)d_in[10];
    const float* bk = (const float*)d_in[11];
    const float* Wv = (const float*)d_in[12];
    const float* bv = (const float*)d_in[13];
    const float* Wo = (const float*)d_in[14];
    const int* cpos = (const int*)d_in[15];
    float* out = (float*)d_out;

    float *pqkv;
    __half *pqh,*pkhf,*pvhf,*pWqkv,*pWo,*pHid,*pAtt;
    cudaGetSymbolAddress((void**)&pqkv,g_qkv);
    cudaGetSymbolAddress((void**)&pqh,g_qh);
    cudaGetSymbolAddress((void**)&pkhf,g_khf);  cudaGetSymbolAddress((void**)&pvhf,g_vhf);
    cudaGetSymbolAddress((void**)&pWqkv,g_Wqkv);cudaGetSymbolAddress((void**)&pWo,g_WoPk);
    cudaGetSymbolAddress((void**)&pHid,g_hidT); cudaGetSymbolAddress((void**)&pAtt,g_attnT);

    // live-cache-only fp16 conversion (independent; runs first)
    merge_cache_kernel<<<(KV_*S_*D_/4)/512, 256>>>(kcache, vcache, cpos, pkhf, pvhf);

    // all weight packs in one launch
    splitA_all_kernel<<<3072, 256>>>(Wq, Wk, Wv, Wo, pWqkv, pWo);
    transpose_splitB_kernel<<<dim3(Q_/32, HID_/32), dim3(32,8)>>>(hidden, pHid);

    // fused QKV projection (M=4096) on fp16 HMMA (proven 128x128 config)
    gemm_pk_kernel<<<dim3(8,32), 256>>>(pWqkv, pHid, bq, bk, bv, pqkv);

    // fused RoPE: Q -> g_qh (fp16, scaled); K/V new tokens -> cache slots (fp16)
    rope_all_kernel<<<dim3(Q_/32, 32), dim3(32,8)>>>(pqkv, cosQD, sinQD, cpos, pqh, pkhf, pvhf);

    // flash attention (fp16, double-buffered K/V)
    const int ATTN_SMEM = 5*64*136*2;   // 87040 B
    cudaFuncSetAttribute(attn_kernel, cudaFuncAttributeMaxDynamicSharedMemorySize, ATTN_SMEM);
    attn_kernel<<<dim3(Q_/64, H_), 128, ATTN_SMEM>>>(pqh, pkhf, pvhf, cpos, pAtt);

    // output projection on fp16 HMMA (no bias)
    gemm_pk_kernel<<<dim3(8,16), 256>>>(pWo, pAtt, nullptr, nullptr, nullptr, out);
}

// round 15
// speedup vs baseline: 1.0677x; 1.0029x over previous
#include <cuda_runtime.h>
#include <cuda_bf16.h>
#include <cuda_fp16.h>
#include <math.h>

#define H_   16
#define KV_  8
#define D_   128
#define HID_ 2048
#define Q_   1024
#define S_   8192
#define K2_  4096

// ---------------- device-global scratch ----------------
__device__ float  g_qkv[4096 * Q_];            // QKV projection [4096][1024] fp32; later reused for Wo split-K partials
__device__ __half g_qh [H_*Q_*D_];             // fp16 Q, RoPE'd, scaled
__device__ __half g_khf[KV_*S_*D_];            // fp16 merged K (cache + new)
__device__ __half g_vhf[KV_*S_*D_];            // fp16 merged V
__device__ __half g_Wqkv[(size_t)4096*K2_];    // A-pack [ah|al] of 64*W
__device__ __half g_WoPk[(size_t)HID_*K2_];
__device__ __half g_hidT[(size_t)Q_*K2_];      // B-pack [bh|bh]
__device__ __half g_attnT[(size_t)Q_*K2_];     // B-pack [bh|bh]

// ---------------- PTX helpers ----------------
__device__ __forceinline__ void ldsm4(unsigned &r0,unsigned &r1,unsigned &r2,unsigned &r3,unsigned a){
    asm volatile("ldmatrix.sync.aligned.m8n8.x4.shared.b16 {%0,%1,%2,%3},[%4];"
                 :"=r"(r0),"=r"(r1),"=r"(r2),"=r"(r3):"r"(a));
}
__device__ __forceinline__ void ldsm4t(unsigned &r0,unsigned &r1,unsigned &r2,unsigned &r3,unsigned a){
    asm volatile("ldmatrix.sync.aligned.m8n8.x4.trans.shared.b16 {%0,%1,%2,%3},[%4];"
                 :"=r"(r0),"=r"(r1),"=r"(r2),"=r"(r3):"r"(a));
}
__device__ __forceinline__ void mma_f16(float c[4], const unsigned a[4], unsigned b0, unsigned b1){
    asm volatile("mma.sync.aligned.m16n8k16.row.col.f32.f16.f16.f32 "
                 "{%0,%1,%2,%3},{%4,%5,%6,%7},{%8,%9},{%0,%1,%2,%3};"
                 :"+f"(c[0]),"+f"(c[1]),"+f"(c[2]),"+f"(c[3])
                 :"r"(a[0]),"r"(a[1]),"r"(a[2]),"r"(a[3]),"r"(b0),"r"(b1));
}
__device__ __forceinline__ void cpa16(unsigned s, const void* g){
    asm volatile("cp.async.cg.shared.global [%0],[%1],16;"::"r"(s),"l"(g));
}
#define CPC()  asm volatile("cp.async.commit_group;")
#define CPW0() asm volatile("cp.async.wait_group 0;")
#define CPW1() asm volatile("cp.async.wait_group 1;")

__device__ __forceinline__ unsigned f2h2(float x, float y){
    __half2 h = __floats2half2_rn(x,y); return *reinterpret_cast<unsigned*>(&h);
}
__device__ __forceinline__ void hilo2h(float x, float y, unsigned &hi, unsigned &lo){
    __half hx=__float2half_rn(x), hy=__float2half_rn(y);
    __half2 hp=__halves2half2(hx,hy); hi=*reinterpret_cast<unsigned*>(&hp);
    __half lx=__float2half_rn(x-__half2float(hx));
    __half ly=__float2half_rn(y-__half2float(hy));
    __half2 lp=__halves2half2(lx,ly); lo=*reinterpret_cast<unsigned*>(&lp);
}

// ---------------- prep: ALL weight A-packs in one launch ----------------
__global__ __launch_bounds__(256)
void splitA_all_kernel(const float* __restrict__ Wq, const float* __restrict__ Wk,
                       const float* __restrict__ Wv, const float* __restrict__ Wo,
                       __half* __restrict__ qkvPk, __half* __restrict__ woPk){
    const size_t base = (size_t)blockIdx.x * 1024;
    const int t = threadIdx.x;
#pragma unroll
    for (int j=0;j<4;j++){
        size_t f = base + j*256 + t;
        const float* src; __half* dst; size_t local;
        if (f < 1048576u)      { src=Wq; dst=qkvPk;                  local=f; }
        else if (f < 1572864u) { src=Wk; dst=qkvPk+(size_t)2048*K2_; local=f-1048576u; }
        else if (f < 2097152u) { src=Wv; dst=qkvPk+(size_t)3072*K2_; local=f-1572864u; }
        else                   { src=Wo; dst=woPk;                   local=f-2097152u; }
        size_t lin = local*4;
        int col = (int)(lin & (HID_-1));
        size_t row = lin >> 11;
        float4 w = *(const float4*)(src + lin);
        unsigned h0,l0,h1,l1;
        hilo2h(w.x*64.f, w.y*64.f, h0, l0);
        hilo2h(w.z*64.f, w.w*64.f, h1, l1);
        size_t b = row*K2_ + col;
        *(uint2*)(dst+b)      = make_uint2(h0,h1);
        *(uint2*)(dst+b+HID_) = make_uint2(l0,l1);
    }
}

// ---------------- prep: hidden [2048][1024] -> hidT B-pack [bh|bh] ----------------
__global__ __launch_bounds__(256)
void transpose_splitB_kernel(const float* __restrict__ src, __half* __restrict__ dst){
    __shared__ float t[32][33];
    const int tx=threadIdx.x, ty=threadIdx.y;          // 32 x 8
    const int n0=blockIdx.x*32, k0=blockIdx.y*32;
#pragma unroll
    for (int r=0;r<4;r++)
        t[ty+8*r][tx] = src[(size_t)(k0+ty+8*r)*Q_ + n0+tx];
    __syncthreads();
#pragma unroll
    for (int r=0;r<4;r++){
        int n = ty+8*r;
        __half hb = __float2half_rn(t[tx][n]);
        size_t b = (size_t)(n0+n)*K2_ + k0+tx;
        dst[b]=hb; dst[b+HID_]=hb;
    }
}

// ---------------- packed-K fp16 GEMM (proven 128x128 config, optional split-K via gridDim.z) ----------------
// C[M][1024] = (A/64)[M][4096]*B[1024][4096]^T (+bias). If gridDim.z==2, each z-half
// covers K2_/2 and writes a partial to C + z*M*Q_ (bias must be null in that case).
__global__ __launch_bounds__(256)
void gemm_pk_kernel(const __half* __restrict__ A, const __half* __restrict__ B,
                    const float* __restrict__ b0, const float* __restrict__ b1,
                    const float* __restrict__ b2, float* __restrict__ C){
    __shared__ __half sA[2][128*40];
    __shared__ __half sB[2][128*40];
    const int tid=threadIdx.x, lane=tid&31, warp=tid>>5;
    const int wm = warp>>1, wn = warp&1;
    const int m0 = blockIdx.y*128, n0 = blockIdx.x*128;
    const int nz = gridDim.z, kz = blockIdx.z;
    const int NKT = 128 / nz;                 // k-steps this CTA
    const int kb  = kz * (K2_ / nz);          // base k offset
    float* Cz = C + (size_t)kz * (size_t)gridDim.y * 128 * Q_;
    const unsigned uA=(unsigned)__cvta_generic_to_shared(&sA[0][0]);
    const unsigned uB=(unsigned)__cvta_generic_to_shared(&sB[0][0]);

    float acc[2][8][4];
#pragma unroll
    for (int a=0;a<2;a++)
#pragma unroll
        for (int b=0;b<8;b++)
#pragma unroll
            for (int c=0;c<4;c++) acc[a][b][c]=0.f;

    auto load=[&](int st,int k0){
#pragma unroll
        for (int i=0;i<2;i++){
            int c = tid + i*256;
            int row = c>>2, seg = c&3;
            cpa16(uA + (st*5120 + row*40 + seg*8)*2, A + (size_t)(m0+row)*K2_ + k0 + seg*8);
            cpa16(uB + (st*5120 + row*40 + seg*8)*2, B + (size_t)(n0+row)*K2_ + k0 + seg*8);
        }
    };
    load(0,kb); CPC();

    for (int kt=0;kt<NKT;kt++){
        int st = kt&1;
        if (kt<NKT-1){ load(st^1, kb+(kt+1)*32); CPC(); CPW1(); } else { CPW0(); }
        __syncthreads();
#pragma unroll
        for (int kh=0;kh<2;kh++){
            unsigned a0[4], a1[4];
            unsigned ao = (unsigned)((st*5120 + (wm*32+(lane&15))*40 + kh*16 + (lane>>4)*8)*2);
            ldsm4(a0[0],a0[1],a0[2],a0[3], uA+ao);
            ldsm4(a1[0],a1[1],a1[2],a1[3], uA+ao + 16*40*2);
            unsigned bf_[8][2];
#pragma unroll
            for (int nt=0;nt<4;nt++){
                unsigned bo = (unsigned)((st*5120 + (wn*64+nt*16+(lane&15))*40 + kh*16 + (lane>>4)*8)*2);
                unsigned r0,r1,r2,r3;
                ldsm4(r0,r1,r2,r3, uB+bo);
                bf_[2*nt][0]=r0; bf_[2*nt][1]=r2; bf_[2*nt+1][0]=r1; bf_[2*nt+1][1]=r3;
            }
#pragma unroll
            for (int nf=0;nf<8;nf++){
                mma_f16(acc[0][nf], a0, bf_[nf][0], bf_[nf][1]);
                mma_f16(acc[1][nf], a1, bf_[nf][0], bf_[nf][1]);
            }
        }
        __syncthreads();
    }
    const float SC = 0.015625f;   // 1/64
#pragma unroll
    for (int mf=0;mf<2;mf++)
#pragma unroll
        for (int nf=0;nf<8;nf++){
            int row = m0 + wm*32 + mf*16 + (lane>>2);
            int col = n0 + wn*64 + nf*8 + (lane&3)*2;
            float bva = 0.f, bvb = 0.f;
            if (b0){
                int r2 = row + 8;
                bva = (row<2048)? b0[row] : ((row<3072)? b1[row-2048] : b2[row-3072]);
                bvb = (r2 <2048)? b0[r2]  : ((r2 <3072)? b1[r2 -2048] : b2[r2 -3072]);
            }
            Cz[(size_t)row*Q_ + col]       = acc[mf][nf][0]*SC + bva;
            Cz[(size_t)row*Q_ + col + 1]   = acc[mf][nf][1]*SC + bva;
            Cz[(size_t)(row+8)*Q_ + col]   = acc[mf][nf][2]*SC + bvb;
            Cz[(size_t)(row+8)*Q_ + col+1] = acc[mf][nf][3]*SC + bvb;
        }
}

// ---------------- split-K reduce: out = p0 + p1 (2M floats each) ----------------
__global__ __launch_bounds__(256)
void addk_kernel(const float* __restrict__ p, float* __restrict__ out){
    size_t i = ((size_t)blockIdx.x*256 + threadIdx.x)*4;
    float4 a = *(const float4*)(p + i);
    float4 b = *(const float4*)(p + i + (size_t)HID_*Q_);
    float4 o = make_float4(a.x+b.x, a.y+b.y, a.z+b.z, a.w+b.w);
    *(float4*)(out + i) = o;
}

// ---------------- fused RoPE: Q->g_qh, K/V new tokens -> cache slots (fp16) ----------------
__global__ __launch_bounds__(256)
void rope_all_kernel(const float* __restrict__ qkv, const float* __restrict__ cosQD,
                     const float* __restrict__ sinQD, const int* __restrict__ cposp,
                     __half* __restrict__ qh, __half* __restrict__ khf,
                     __half* __restrict__ vhf){
    __shared__ float tile[128][33];
    const int tx=threadIdx.x, ty=threadIdx.y;          // 32 x 8
    const int i0=blockIdx.x*32, slot=blockIdx.y;
    const int cpos = cposp[0];

    int srcrow; __half* dst; size_t drow0; int do_rope; float scale;
    if (slot < 16){ srcrow = slot*128;            dst=qh;  drow0=(size_t)slot*Q_ + i0;        do_rope=1; scale=0.08838834764831845f; }
    else if (slot < 24){ int kv=slot-16; srcrow = 2048 + kv*128; dst=khf; drow0=(size_t)kv*S_ + cpos + i0; do_rope=1; scale=1.f; }
    else { int kv=slot-24; srcrow = 3072 + kv*128; dst=vhf; drow0=(size_t)kv*S_ + cpos + i0; do_rope=0; scale=1.f; }

#pragma unroll
    for (int r=0;r<16;r++)
        tile[r*8+ty][tx] = qkv[(size_t)(srcrow + r*8+ty)*Q_ + i0+tx];
    __syncthreads();
    const int t = ty*32+tx;
#pragma unroll
    for (int r=0;r<16;r++){
        int idx = r*256 + t;
        int d = idx & 127, i = idx >> 7;
        float v = tile[d][i], outv;
        if (do_rope){
            float o = (d<64) ? -tile[d+64][i] : tile[d-64][i];
            outv = (v*cosQD[(size_t)(i0+i)*128+d] + o*sinQD[(size_t)(i0+i)*128+d])*scale;
        } else outv = v;
        dst[(drow0 + i)*128 + d] = __float2half_rn(outv);
    }
}

// ---------------- cache fp16 conversion — only slots attention can read ----------------
__global__ __launch_bounds__(256)
void merge_cache_kernel(const float* __restrict__ kc_, const float* __restrict__ vc_,
                        const int* __restrict__ cposp,
                        __half* __restrict__ khf, __half* __restrict__ vhf){
    const int cpos = cposp[0];
    const size_t base = (size_t)blockIdx.x * 512;
#pragma unroll
    for (int j=0;j<2;j++){
        size_t idx = base + j*256 + threadIdx.x;
        size_t lin = idx*4;
        int s = (int)((lin>>7) & (S_-1));
        if (s >= cpos) continue;          // [cpos,cpos+Q) by rope_all; [cpos+Q,S) never read
        float4 k4 = *(const float4*)(kc_+lin);
        float4 v4 = *(const float4*)(vc_+lin);
        *(uint2*)(khf+lin) = make_uint2(f2h2(k4.x,k4.y), f2h2(k4.z,k4.w));
        *(uint2*)(vhf+lin) = make_uint2(f2h2(v4.x,v4.y), f2h2(v4.z,v4.w));
    }
}

// ---------------- flash attention, fp16 MMA, double-buffered K/V ----------------
__global__ __launch_bounds__(128)
void attn_kernel(const __half* __restrict__ qh, const __half* __restrict__ khf,
                 const __half* __restrict__ vhf, const int* __restrict__ cposp,
                 __half* __restrict__ attnT){
    extern __shared__ __half smh[];
    const int TS = 64*136;
    const int tid=threadIdx.x, lane=tid&31, w=tid>>5;
    const int q0=blockIdx.x*64, h=blockIdx.y, kv=h>>1;
    const int cpos = cposp[0];
    const unsigned sb=(unsigned)__cvta_generic_to_shared(smh);
    const unsigned uQ=sb;
    const unsigned uKb[2] = { sb+TS*2,   sb+3*TS*2 };
    const unsigned uVb[2] = { sb+2*TS*2, sb+4*TS*2 };

#pragma unroll
    for (int i=0;i<8;i++){
        int c = tid + i*128;
        int row = c>>4, seg = c&15;
        cpa16(uQ + (unsigned)((row*136 + seg*8)*2),
              qh + ((size_t)h*Q_ + q0 + row)*128 + seg*8);
    }
    CPC();

    auto ldkv = [&](int sbk, int buf){
        int s0 = sbk*64;
#pragma unroll
        for (int i=0;i<8;i++){
            int c = tid + i*128;
            int row = c>>4, seg = c&15;
            size_t gk = ((size_t)kv*S_ + s0 + row)*128 + seg*8;
            unsigned so = (unsigned)((row*136 + seg*8)*2);
            cpa16(uKb[buf]+so, khf+gk);
            cpa16(uVb[buf]+so, vhf+gk);
        }
        CPC();
    };

    float out[16][4];
#pragma unroll
    for (int a=0;a<16;a++)
#pragma unroll
        for (int c=0;c<4;c++) out[a][c]=0.f;
    float m0=-1e30f, m1=-1e30f, l0=0.f, l1=0.f;
    const int r0 = lane>>2, qb = q0 + w*16;

    int nblk = (cpos + q0 + 63)/64 + 1;
    if (nblk > S_/64) nblk = S_/64;

    ldkv(0,0);

    for (int sbk=0; sbk<nblk; sbk++){
        const int s0 = sbk*64;
        const int b = sbk&1;
        if (sbk+1 < nblk){ ldkv(sbk+1, b^1); CPW1(); } else { CPW0(); }
        __syncthreads();
        const unsigned uK = uKb[b], uV = uVb[b];

        float sc[8][4];
#pragma unroll
        for (int a=0;a<8;a++)
#pragma unroll
            for (int c=0;c<4;c++) sc[a][c]=0.f;
#pragma unroll
        for (int kd=0;kd<8;kd++){
            unsigned aq[4];
            unsigned qo = (unsigned)(((w*16+(lane&15))*136 + kd*16 + (lane>>4)*8)*2);
            ldsm4(aq[0],aq[1],aq[2],aq[3], uQ+qo);
#pragma unroll
            for (int nt=0;nt<4;nt++){
                unsigned ko = (unsigned)(((nt*16+(lane&15))*136 + kd*16 + (lane>>4)*8)*2);
                unsigned k0r,k1r,k2r,k3r;
                ldsm4(k0r,k1r,k2r,k3r, uK+ko);
                mma_f16(sc[2*nt],   aq, k0r,k2r);
                mma_f16(sc[2*nt+1], aq, k1r,k3r);
            }
        }

        if (s0 + 63 > cpos + qb){
            int lim0 = cpos + qb + r0, lim1 = lim0 + 8;
#pragma unroll
            for (int nf=0;nf<8;nf++){
                int j = s0 + nf*8 + 2*(lane&3);
                if (j   > lim0) sc[nf][0] = -1e30f;
                if (j+1 > lim0) sc[nf][1] = -1e30f;
                if (j   > lim1) sc[nf][2] = -1e30f;
                if (j+1 > lim1) sc[nf][3] = -1e30f;
            }
        }

        float mx0=-1e30f, mx1=-1e30f;
#pragma unroll
        for (int nf=0;nf<8;nf++){
            mx0 = fmaxf(mx0, fmaxf(sc[nf][0], sc[nf][1]));
            mx1 = fmaxf(mx1, fmaxf(sc[nf][2], sc[nf][3]));
        }
        mx0 = fmaxf(mx0, __shfl_xor_sync(0xffffffffu, mx0, 1));
        mx0 = fmaxf(mx0, __shfl_xor_sync(0xffffffffu, mx0, 2));
        mx1 = fmaxf(mx1, __shfl_xor_sync(0xffffffffu, mx1, 1));
        mx1 = fmaxf(mx1, __shfl_xor_sync(0xffffffffu, mx1, 2));
        float n0_ = fmaxf(m0, mx0), n1_ = fmaxf(m1, mx1);
        float s0f = __expf(m0 - n0_), s1f = __expf(m1 - n1_);
        m0 = n0_; m1 = n1_;
        float ps0=0.f, ps1=0.f;
#pragma unroll
        for (int nf=0;nf<8;nf++){
            sc[nf][0]=__expf(sc[nf][0]-m0); ps0+=sc[nf][0];
            sc[nf][1]=__expf(sc[nf][1]-m0); ps0+=sc[nf][1];
            sc[nf][2]=__expf(sc[nf][2]-m1); ps1+=sc[nf][2];
            sc[nf][3]=__expf(sc[nf][3]-m1); ps1+=sc[nf][3];
        }
        ps0 += __shfl_xor_sync(0xffffffffu, ps0, 1);
        ps0 += __shfl_xor_sync(0xffffffffu, ps0, 2);
        ps1 += __shfl_xor_sync(0xffffffffu, ps1, 1);
        ps1 += __shfl_xor_sync(0xffffffffu, ps1, 2);
        l0 = l0*s0f + ps0;
        l1 = l1*s1f + ps1;
#pragma unroll
        for (int df=0;df<16;df++){
            out[df][0]*=s0f; out[df][1]*=s0f; out[df][2]*=s1f; out[df][3]*=s1f;
        }

#pragma unroll
        for (int kc=0;kc<4;kc++){
            unsigned ph[4];
            ph[0] = f2h2(sc[2*kc][0],   sc[2*kc][1]);
            ph[1] = f2h2(sc[2*kc][2],   sc[2*kc][3]);
            ph[2] = f2h2(sc[2*kc+1][0], sc[2*kc+1][1]);
            ph[3] = f2h2(sc[2*kc+1][2], sc[2*kc+1][3]);
#pragma unroll
            for (int dt=0;dt<8;dt++){
                unsigned vo = (unsigned)(((kc*16+(lane&15))*136 + dt*16 + (lane>>4)*8)*2);
                unsigned v0,v1,v2,v3;
                ldsm4t(v0,v1,v2,v3, uV+vo);
                mma_f16(out[2*dt],   ph, v0,v1);
                mma_f16(out[2*dt+1], ph, v2,v3);
            }
        }
        __syncthreads();
    }

    float inv0 = 1.f/l0, inv1 = 1.f/l1;
    int qrow0 = qb + r0, qrow1 = qrow0 + 8;
#pragma unroll
    for (int df=0;df<16;df++){
        int colg = h*128 + df*8 + (lane&3)*2;
        unsigned hv;
        hv = f2h2(out[df][0]*inv0, out[df][1]*inv0);
        *(unsigned*)(attnT + (size_t)qrow0*K2_ + colg)        = hv;
        *(unsigned*)(attnT + (size_t)qrow0*K2_ + 2048 + colg) = hv;
        hv = f2h2(out[df][2]*inv1, out[df][3]*inv1);
        *(unsigned*)(attnT + (size_t)qrow1*K2_ + colg)        = hv;
        *(unsigned*)(attnT + (size_t)qrow1*K2_ + 2048 + colg) = hv;
    }
}

// ---------------- launch ----------------
extern "C" void kernel_launch(void* const* d_in, const int* in_sizes, int n_in,
                              void* d_out, int out_size){
    const float* hidden = (const float*)d_in[0];
    const float* cosQD  = (const float*)d_in[1];
    const float* sinQD  = (const float*)d_in[2];
    const float* kcache = (const float*)d_in[6];
    const float* vcache = (const float*)d_in[7];
    const float* Wq = (const float*)d_in[8];
    const float* bq = (const float*)d_in[9];
    const float* Wk = (const float*)d_in[10];
    const float* bk = (const float*)d_in[11];
    const float* Wv = (const float*)d_in[12];
    const float* bv = (const float*)d_in[13];
    const float* Wo = (const float*)d_in[14];
    const int* cpos = (const int*)d_in[15];
    float* out = (float*)d_out;

    float *pqkv;
    __half *pqh,*pkhf,*pvhf,*pWqkv,*pWo,*pHid,*pAtt;
    cudaGetSymbolAddress((void**)&pqkv,g_qkv);
    cudaGetSymbolAddress((void**)&pqh,g_qh);
    cudaGetSymbolAddress((void**)&pkhf,g_khf);  cudaGetSymbolAddress((void**)&pvhf,g_vhf);
    cudaGetSymbolAddress((void**)&pWqkv,g_Wqkv);cudaGetSymbolAddress((void**)&pWo,g_WoPk);
    cudaGetSymbolAddress((void**)&pHid,g_hidT); cudaGetSymbolAddress((void**)&pAtt,g_attnT);

    // live-cache-only fp16 conversion (independent; runs first)
    merge_cache_kernel<<<(KV_*S_*D_/4)/512, 256>>>(kcache, vcache, cpos, pkhf, pvhf);

    // all weight packs in one launch
    splitA_all_kernel<<<3072, 256>>>(Wq, Wk, Wv, Wo, pWqkv, pWo);
    transpose_splitB_kernel<<<dim3(Q_/32, HID_/32), dim3(32,8)>>>(hidden, pHid);

    // fused QKV projection (M=4096) on fp16 HMMA (single wave, 256 CTAs)
    gemm_pk_kernel<<<dim3(8,32,1), 256>>>(pWqkv, pHid, bq, bk, bv, pqkv);

    // fused RoPE: Q -> g_qh (fp16, scaled); K/V new tokens -> cache slots (fp16)
    // (after this, g_qkv is dead and reusable as Wo split-K partial buffer)
    rope_all_kernel<<<dim3(Q_/32, 32), dim3(32,8)>>>(pqkv, cosQD, sinQD, cpos, pqh, pkhf, pvhf);

    // flash attention (fp16, double-buffered K/V)
    const int ATTN_SMEM = 5*64*136*2;   // 87040 B
    cudaFuncSetAttribute(attn_kernel, cudaFuncAttributeMaxDynamicSharedMemorySize, ATTN_SMEM);
    attn_kernel<<<dim3(Q_/64, H_), 128, ATTN_SMEM>>>(pqh, pkhf, pvhf, cpos, pAtt);

    // output projection: split-K=2 into g_qkv partials (256 CTAs), then reduce
    gemm_pk_kernel<<<dim3(8,16,2), 256>>>(pWo, pAtt, nullptr, nullptr, nullptr, pqkv);
    addk_kernel<<<(HID_*Q_/4)/256, 256>>>(pqkv, out);
}

// round 17
// speedup vs baseline: 1.1249x; 1.0536x over previous
#include <cuda_runtime.h>
#include <cuda_bf16.h>
#include <cuda_fp16.h>
#include <math.h>

#define H_   16
#define KV_  8
#define D_   128
#define HID_ 2048
#define Q_   1024
#define S_   8192
#define K2_  4096
#define KB_  2048

// ---------------- device-global scratch ----------------
__device__ float  g_qkv[4096 * Q_];            // QKV projection; reused for Wo split-K partials
__device__ __half g_qh [H_*Q_*D_];
__device__ __half g_khf[KV_*S_*D_];
__device__ __half g_vhf[KV_*S_*D_];
__device__ __half g_Wqkv[(size_t)4096*K2_];    // A-pack [ah|al] of 64*W (K=4096)
__device__ __half g_WoPk[(size_t)HID_*K2_];
__device__ __half g_hidT[(size_t)Q_*KB_];      // B single [bh] (K=2048)
__device__ __half g_attnT[(size_t)Q_*KB_];     // B single [bh]

// ---------------- PTX helpers ----------------
__device__ __forceinline__ void ldsm4(unsigned &r0,unsigned &r1,unsigned &r2,unsigned &r3,unsigned a){
    asm volatile("ldmatrix.sync.aligned.m8n8.x4.shared.b16 {%0,%1,%2,%3},[%4];"
                 :"=r"(r0),"=r"(r1),"=r"(r2),"=r"(r3):"r"(a));
}
__device__ __forceinline__ void ldsm4t(unsigned &r0,unsigned &r1,unsigned &r2,unsigned &r3,unsigned a){
    asm volatile("ldmatrix.sync.aligned.m8n8.x4.trans.shared.b16 {%0,%1,%2,%3},[%4];"
                 :"=r"(r0),"=r"(r1),"=r"(r2),"=r"(r3):"r"(a));
}
__device__ __forceinline__ void mma_f16(float c[4], const unsigned a[4], unsigned b0, unsigned b1){
    asm volatile("mma.sync.aligned.m16n8k16.row.col.f32.f16.f16.f32 "
                 "{%0,%1,%2,%3},{%4,%5,%6,%7},{%8,%9},{%0,%1,%2,%3};"
                 :"+f"(c[0]),"+f"(c[1]),"+f"(c[2]),"+f"(c[3])
                 :"r"(a[0]),"r"(a[1]),"r"(a[2]),"r"(a[3]),"r"(b0),"r"(b1));
}
__device__ __forceinline__ void cpa16(unsigned s, const void* g){
    asm volatile("cp.async.cg.shared.global [%0],[%1],16;"::"r"(s),"l"(g));
}
#define CPC()  asm volatile("cp.async.commit_group;")
#define CPW0() asm volatile("cp.async.wait_group 0;")
#define CPW1() asm volatile("cp.async.wait_group 1;")

__device__ __forceinline__ unsigned f2h2(float x, float y){
    __half2 h = __floats2half2_rn(x,y); return *reinterpret_cast<unsigned*>(&h);
}
__device__ __forceinline__ void hilo2h(float x, float y, unsigned &hi, unsigned &lo){
    __half hx=__float2half_rn(x), hy=__float2half_rn(y);
    __half2 hp=__halves2half2(hx,hy); hi=*reinterpret_cast<unsigned*>(&hp);
    __half lx=__float2half_rn(x-__half2float(hx));
    __half ly=__float2half_rn(y-__half2float(hy));
    __half2 lp=__halves2half2(lx,ly); lo=*reinterpret_cast<unsigned*>(&lp);
}

// ---------------- prep: ALL weight A-packs in one launch ----------------
__global__ __launch_bounds__(256)
void splitA_all_kernel(const float* __restrict__ Wq, const float* __restrict__ Wk,
                       const float* __restrict__ Wv, const float* __restrict__ Wo,
                       __half* __restrict__ qkvPk, __half* __restrict__ woPk){
    const size_t base = (size_t)blockIdx.x * 1024;
    const int t = threadIdx.x;
#pragma unroll
    for (int j=0;j<4;j++){
        size_t f = base + j*256 + t;
        const float* src; __half* dst; size_t local;
        if (f < 1048576u)      { src=Wq; dst=qkvPk;                  local=f; }
        else if (f < 1572864u) { src=Wk; dst=qkvPk+(size_t)2048*K2_; local=f-1048576u; }
        else if (f < 2097152u) { src=Wv; dst=qkvPk+(size_t)3072*K2_; local=f-1572864u; }
        else                   { src=Wo; dst=woPk;                   local=f-2097152u; }
        size_t lin = local*4;
        int col = (int)(lin & (HID_-1));
        size_t row = lin >> 11;
        float4 w = *(const float4*)(src + lin);
        unsigned h0,l0,h1,l1;
        hilo2h(w.x*64.f, w.y*64.f, h0, l0);
        hilo2h(w.z*64.f, w.w*64.f, h1, l1);
        size_t b = row*K2_ + col;
        *(uint2*)(dst+b)      = make_uint2(h0,h1);
        *(uint2*)(dst+b+HID_) = make_uint2(l0,l1);
    }
}

// ---------------- prep: hidden [2048][1024] -> hidT [1024][2048] single bh ----------------
__global__ __launch_bounds__(256)
void transpose_splitB_kernel(const float* __restrict__ src, __half* __restrict__ dst){
    __shared__ float t[32][33];
    const int tx=threadIdx.x, ty=threadIdx.y;          // 32 x 8
    const int n0=blockIdx.x*32, k0=blockIdx.y*32;
#pragma unroll
    for (int r=0;r<4;r++)
        t[ty+8*r][tx] = src[(size_t)(k0+ty+8*r)*Q_ + n0+tx];
    __syncthreads();
#pragma unroll
    for (int r=0;r<4;r++){
        int n = ty+8*r;
        dst[(size_t)(n0+n)*KB_ + k0+tx] = __float2half_rn(t[tx][n]);
    }
}

// ---------------- packed fp16 GEMM with B reuse: C = (Ah+Al)/64 * Bh^T (+bias) ----------------
// A: [M][4096] = [ah|al]; B: [1024][2048]. 128x128 tile, k-step 32 over KB_=2048,
// each B fragment reused for ah and al. Split-K via gridDim.z.
// Dyn smem: 2 stages x 30720 B; within a stage (BYTE offsets): Ah@0, Al@10240, B@20480.
__global__ __launch_bounds__(256)
void gemm_pk_kernel(const __half* __restrict__ A, const __half* __restrict__ B,
                    const float* __restrict__ b0, const float* __restrict__ b1,
                    const float* __restrict__ b2, float* __restrict__ C){
    extern __shared__ __half gsm[];
    const int tid=threadIdx.x, lane=tid&31, warp=tid>>5;
    const int wm = warp>>1, wn = warp&1;
    const int m0 = blockIdx.y*128, n0 = blockIdx.x*128;
    const int nz = gridDim.z, kz = blockIdx.z;
    const int NKT = 64 / nz;
    const int kb  = kz * (KB_ / nz);
    float* Cz = C + (size_t)kz * (size_t)gridDim.y * 128 * Q_;
    const unsigned uS=(unsigned)__cvta_generic_to_shared(gsm);

    float acc[2][8][4];
#pragma unroll
    for (int a=0;a<2;a++)
#pragma unroll
        for (int b=0;b<8;b++)
#pragma unroll
            for (int c=0;c<4;c++) acc[a][b][c]=0.f;

    auto load=[&](int st,int k0){
        unsigned sb = (unsigned)st*30720u;   // stage base, BYTES
#pragma unroll
        for (int i=0;i<2;i++){
            int c = tid + i*256;
            int row = c>>2, seg = c&3;
            unsigned off = (unsigned)((row*40 + seg*8)*2);
            cpa16(uS + sb + off,         A + (size_t)(m0+row)*K2_ + k0 + seg*8);          // ah
            cpa16(uS + sb + 10240 + off, A + (size_t)(m0+row)*K2_ + 2048 + k0 + seg*8);   // al
            cpa16(uS + sb + 20480 + off, B + (size_t)(n0+row)*KB_ + k0 + seg*8);          // bh
        }
    };
    load(0,kb); CPC();

    for (int kt=0;kt<NKT;kt++){
        int st = kt&1;
        if (kt<NKT-1){ load(st^1, kb+(kt+1)*32); CPC(); CPW1(); } else { CPW0(); }
        __syncthreads();
        unsigned sb = (unsigned)st*30720u;   // BYTES
#pragma unroll
        for (int kh=0;kh<2;kh++){
            unsigned frag = (unsigned)(((wm*32+(lane&15))*40 + kh*16 + (lane>>4)*8)*2);
            unsigned ah0[4], ah1[4], al0[4], al1[4];
            ldsm4(ah0[0],ah0[1],ah0[2],ah0[3], uS+sb+frag);
            ldsm4(ah1[0],ah1[1],ah1[2],ah1[3], uS+sb+frag + 16*40*2);
            ldsm4(al0[0],al0[1],al0[2],al0[3], uS+sb+10240+frag);
            ldsm4(al1[0],al1[1],al1[2],al1[3], uS+sb+10240+frag + 16*40*2);
            unsigned bf_[8][2];
#pragma unroll
            for (int nt=0;nt<4;nt++){
                unsigned bo = (unsigned)(sb + 20480 + ((wn*64+nt*16+(lane&15))*40 + kh*16 + (lane>>4)*8)*2);
                unsigned r0,r1,r2,r3;
                ldsm4(r0,r1,r2,r3, uS+bo);
                bf_[2*nt][0]=r0; bf_[2*nt][1]=r2; bf_[2*nt+1][0]=r1; bf_[2*nt+1][1]=r3;
            }
#pragma unroll
            for (int nf=0;nf<8;nf++){
                mma_f16(acc[0][nf], ah0, bf_[nf][0], bf_[nf][1]);
                mma_f16(acc[0][nf], al0, bf_[nf][0], bf_[nf][1]);
                mma_f16(acc[1][nf], ah1, bf_[nf][0], bf_[nf][1]);
                mma_f16(acc[1][nf], al1, bf_[nf][0], bf_[nf][1]);
            }
        }
        __syncthreads();
    }
    const float SC = 0.015625f;   // 1/64
#pragma unroll
    for (int mf=0;mf<2;mf++)
#pragma unroll
        for (int nf=0;nf<8;nf++){
            int row = m0 + wm*32 + mf*16 + (lane>>2);
            int col = n0 + wn*64 + nf*8 + (lane&3)*2;
            float bva = 0.f, bvb = 0.f;
            if (b0){
                int r2 = row + 8;
                bva = (row<2048)? b0[row] : ((row<3072)? b1[row-2048] : b2[row-3072]);
                bvb = (r2 <2048)? b0[r2]  : ((r2 <3072)? b1[r2 -2048] : b2[r2 -3072]);
            }
            Cz[(size_t)row*Q_ + col]       = acc[mf][nf][0]*SC + bva;
            Cz[(size_t)row*Q_ + col + 1]   = acc[mf][nf][1]*SC + bva;
            Cz[(size_t)(row+8)*Q_ + col]   = acc[mf][nf][2]*SC + bvb;
            Cz[(size_t)(row+8)*Q_ + col+1] = acc[mf][nf][3]*SC + bvb;
        }
}
#define GEMM_SMEM 61440

// ---------------- split-K reduce ----------------
__global__ __launch_bounds__(256)
void addk_kernel(const float* __restrict__ p, float* __restrict__ out){
    size_t i = ((size_t)blockIdx.x*256 + threadIdx.x)*4;
    float4 a = *(const float4*)(p + i);
    float4 b = *(const float4*)(p + i + (size_t)HID_*Q_);
    *(float4*)(out + i) = make_float4(a.x+b.x, a.y+b.y, a.z+b.z, a.w+b.w);
}

// ---------------- fused RoPE ----------------
__global__ __launch_bounds__(256)
void rope_all_kernel(const float* __restrict__ qkv, const float* __restrict__ cosQD,
                     const float* __restrict__ sinQD, const int* __restrict__ cposp,
                     __half* __restrict__ qh, __half* __restrict__ khf,
                     __half* __restrict__ vhf){
    __shared__ float tile[128][33];
    const int tx=threadIdx.x, ty=threadIdx.y;
    const int i0=blockIdx.x*32, slot=blockIdx.y;
    const int cpos = cposp[0];

    int srcrow; __half* dst; size_t drow0; int do_rope; float scale;
    if (slot < 16){ srcrow = slot*128;            dst=qh;  drow0=(size_t)slot*Q_ + i0;        do_rope=1; scale=0.08838834764831845f; }
    else if (slot < 24){ int kv=slot-16; srcrow = 2048 + kv*128; dst=khf; drow0=(size_t)kv*S_ + cpos + i0; do_rope=1; scale=1.f; }
    else { int kv=slot-24; srcrow = 3072 + kv*128; dst=vhf; drow0=(size_t)kv*S_ + cpos + i0; do_rope=0; scale=1.f; }

#pragma unroll
    for (int r=0;r<16;r++)
        tile[r*8+ty][tx] = qkv[(size_t)(srcrow + r*8+ty)*Q_ + i0+tx];
    __syncthreads();
    const int t = ty*32+tx;
#pragma unroll
    for (int r=0;r<16;r++){
        int idx = r*256 + t;
        int d = idx & 127, i = idx >> 7;
        float v = tile[d][i], outv;
        if (do_rope){
            float o = (d<64) ? -tile[d+64][i] : tile[d-64][i];
            outv = (v*cosQD[(size_t)(i0+i)*128+d] + o*sinQD[(size_t)(i0+i)*128+d])*scale;
        } else outv = v;
        dst[(drow0 + i)*128 + d] = __float2half_rn(outv);
    }
}

// ---------------- cache fp16 conversion — only live slots ----------------
__global__ __launch_bounds__(256)
void merge_cache_kernel(const float* __restrict__ kc_, const float* __restrict__ vc_,
                        const int* __restrict__ cposp,
                        __half* __restrict__ khf, __half* __restrict__ vhf){
    const int cpos = cposp[0];
    const size_t base = (size_t)blockIdx.x * 512;
#pragma unroll
    for (int j=0;j<2;j++){
        size_t idx = base + j*256 + threadIdx.x;
        size_t lin = idx*4;
        int s = (int)((lin>>7) & (S_-1));
        if (s >= cpos) continue;
        float4 k4 = *(const float4*)(kc_+lin);
        float4 v4 = *(const float4*)(vc_+lin);
        *(uint2*)(khf+lin) = make_uint2(f2h2(k4.x,k4.y), f2h2(k4.z,k4.w));
        *(uint2*)(vhf+lin) = make_uint2(f2h2(v4.x,v4.y), f2h2(v4.z,v4.w));
    }
}

// ---------------- flash attention, fp16 MMA, double-buffered K/V ----------------
__global__ __launch_bounds__(128)
void attn_kernel(const __half* __restrict__ qh, const __half* __restrict__ khf,
                 const __half* __restrict__ vhf, const int* __restrict__ cposp,
                 __half* __restrict__ attnT){
    extern __shared__ __half smh[];
    const int TS = 64*136;
    const int tid=threadIdx.x, lane=tid&31, w=tid>>5;
    const int q0=blockIdx.x*64, h=blockIdx.y, kv=h>>1;
    const int cpos = cposp[0];
    const unsigned sb=(unsigned)__cvta_generic_to_shared(smh);
    const unsigned uQ=sb;
    const unsigned uKb[2] = { sb+TS*2,   sb+3*TS*2 };
    const unsigned uVb[2] = { sb+2*TS*2, sb+4*TS*2 };

#pragma unroll
    for (int i=0;i<8;i++){
        int c = tid + i*128;
        int row = c>>4, seg = c&15;
        cpa16(uQ + (unsigned)((row*136 + seg*8)*2),
              qh + ((size_t)h*Q_ + q0 + row)*128 + seg*8);
    }
    CPC();

    auto ldkv = [&](int sbk, int buf){
        int s0 = sbk*64;
#pragma unroll
        for (int i=0;i<8;i++){
            int c = tid + i*128;
            int row = c>>4, seg = c&15;
            size_t gk = ((size_t)kv*S_ + s0 + row)*128 + seg*8;
            unsigned so = (unsigned)((row*136 + seg*8)*2);
            cpa16(uKb[buf]+so, khf+gk);
            cpa16(uVb[buf]+so, vhf+gk);
        }
        CPC();
    };

    float out[16][4];
#pragma unroll
    for (int a=0;a<16;a++)
#pragma unroll
        for (int c=0;c<4;c++) out[a][c]=0.f;
    float m0=-1e30f, m1=-1e30f, l0=0.f, l1=0.f;
    const int r0 = lane>>2, qb = q0 + w*16;

    int nblk = (cpos + q0 + 63)/64 + 1;
    if (nblk > S_/64) nblk = S_/64;

    ldkv(0,0);

    for (int sbk=0; sbk<nblk; sbk++){
        const int s0 = sbk*64;
        const int b = sbk&1;
        if (sbk+1 < nblk){ ldkv(sbk+1, b^1); CPW1(); } else { CPW0(); }
        __syncthreads();
        const unsigned uK = uKb[b], uV = uVb[b];

        float sc[8][4];
#pragma unroll
        for (int a=0;a<8;a++)
#pragma unroll
            for (int c=0;c<4;c++) sc[a][c]=0.f;
#pragma unroll
        for (int kd=0;kd<8;kd++){
            unsigned aq[4];
            unsigned qo = (unsigned)(((w*16+(lane&15))*136 + kd*16 + (lane>>4)*8)*2);
            ldsm4(aq[0],aq[1],aq[2],aq[3], uQ+qo);
#pragma unroll
            for (int nt=0;nt<4;nt++){
                unsigned ko = (unsigned)(((nt*16+(lane&15))*136 + kd*16 + (lane>>4)*8)*2);
                unsigned k0r,k1r,k2r,k3r;
                ldsm4(k0r,k1r,k2r,k3r, uK+ko);
                mma_f16(sc[2*nt],   aq, k0r,k2r);
                mma_f16(sc[2*nt+1], aq, k1r,k3r);
            }
        }

        if (s0 + 63 > cpos + qb){
            int lim0 = cpos + qb + r0, lim1 = lim0 + 8;
#pragma unroll
            for (int nf=0;nf<8;nf++){
                int j = s0 + nf*8 + 2*(lane&3);
                if (j   > lim0) sc[nf][0] = -1e30f;
                if (j+1 > lim0) sc[nf][1] = -1e30f;
                if (j   > lim1) sc[nf][2] = -1e30f;
                if (j+1 > lim1) sc[nf][3] = -1e30f;
            }
        }

        float mx0=-1e30f, mx1=-1e30f;
#pragma unroll
        for (int nf=0;nf<8;nf++){
            mx0 = fmaxf(mx0, fmaxf(sc[nf][0], sc[nf][1]));
            mx1 = fmaxf(mx1, fmaxf(sc[nf][2], sc[nf][3]));
        }
        mx0 = fmaxf(mx0, __shfl_xor_sync(0xffffffffu, mx0, 1));
        mx0 = fmaxf(mx0, __shfl_xor_sync(0xffffffffu, mx0, 2));
        mx1 = fmaxf(mx1, __shfl_xor_sync(0xffffffffu, mx1, 1));
        mx1 = fmaxf(mx1, __shfl_xor_sync(0xffffffffu, mx1, 2));
        float n0_ = fmaxf(m0, mx0), n1_ = fmaxf(m1, mx1);
        float s0f = __expf(m0 - n0_), s1f = __expf(m1 - n1_);
        m0 = n0_; m1 = n1_;
        float ps0=0.f, ps1=0.f;
#pragma unroll
        for (int nf=0;nf<8;nf++){
            sc[nf][0]=__expf(sc[nf][0]-m0); ps0+=sc[nf][0];
            sc[nf][1]=__expf(sc[nf][1]-m0); ps0+=sc[nf][1];
            sc[nf][2]=__expf(sc[nf][2]-m1); ps1+=sc[nf][2];
            sc[nf][3]=__expf(sc[nf][3]-m1); ps1+=sc[nf][3];
        }
        ps0 += __shfl_xor_sync(0xffffffffu, ps0, 1);
        ps0 += __shfl_xor_sync(0xffffffffu, ps0, 2);
        ps1 += __shfl_xor_sync(0xffffffffu, ps1, 1);
        ps1 += __shfl_xor_sync(0xffffffffu, ps1, 2);
        l0 = l0*s0f + ps0;
        l1 = l1*s1f + ps1;
#pragma unroll
        for (int df=0;df<16;df++){
            out[df][0]*=s0f; out[df][1]*=s0f; out[df][2]*=s1f; out[df][3]*=s1f;
        }

#pragma unroll
        for (int kc=0;kc<4;kc++){
            unsigned ph[4];
            ph[0] = f2h2(sc[2*kc][0],   sc[2*kc][1]);
            ph[1] = f2h2(sc[2*kc][2],   sc[2*kc][3]);
            ph[2] = f2h2(sc[2*kc+1][0], sc[2*kc+1][1]);
            ph[3] = f2h2(sc[2*kc+1][2], sc[2*kc+1][3]);
#pragma unroll
            for (int dt=0;dt<8;dt++){
                unsigned vo = (unsigned)(((kc*16+(lane&15))*136 + dt*16 + (lane>>4)*8)*2);
                unsigned v0,v1,v2,v3;
                ldsm4t(v0,v1,v2,v3, uV+vo);
                mma_f16(out[2*dt],   ph, v0,v1);
                mma_f16(out[2*dt+1], ph, v2,v3);
            }
        }
        __syncthreads();
    }

    float inv0 = 1.f/l0, inv1 = 1.f/l1;
    int qrow0 = qb + r0, qrow1 = qrow0 + 8;
#pragma unroll
    for (int df=0;df<16;df++){
        int colg = h*128 + df*8 + (lane&3)*2;
        *(unsigned*)(attnT + (size_t)qrow0*KB_ + colg) = f2h2(out[df][0]*inv0, out[df][1]*inv0);
        *(unsigned*)(attnT + (size_t)qrow1*KB_ + colg) = f2h2(out[df][2]*inv1, out[df][3]*inv1);
    }
}

// ---------------- launch ----------------
extern "C" void kernel_launch(void* const* d_in, const int* in_sizes, int n_in,
                              void* d_out, int out_size){
    const float* hidden = (const float*)d_in[0];
    const float* cosQD  = (const float*)d_in[1];
    const float* sinQD  = (const float*)d_in[2];
    const float* kcache = (const float*)d_in[6];
    const float* vcache = (const float*)d_in[7];
    const float* Wq = (const float*)d_in[8];
    const float* bq = (const float*)d_in[9];
    const float* Wk = (const float*)d_in[10];
    const float* bk = (const float*)d_in[11];
    const float* Wv = (const float*)d_in[12];
    const float* bv = (const float*)d_in[13];
    const float* Wo = (const float*)d_in[14];
    const int* cpos = (const int*)d_in[15];
    float* out = (float*)d_out;

    float *pqkv;
    __half *pqh,*pkhf,*pvhf,*pWqkv,*pWo,*pHid,*pAtt;
    cudaGetSymbolAddress((void**)&pqkv,g_qkv);
    cudaGetSymbolAddress((void**)&pqh,g_qh);
    cudaGetSymbolAddress((void**)&pkhf,g_khf);  cudaGetSymbolAddress((void**)&pvhf,g_vhf);
    cudaGetSymbolAddress((void**)&pWqkv,g_Wqkv);cudaGetSymbolAddress((void**)&pWo,g_WoPk);
    cudaGetSymbolAddress((void**)&pHid,g_hidT); cudaGetSymbolAddress((void**)&pAtt,g_attnT);

    merge_cache_kernel<<<(KV_*S_*D_/4)/512, 256>>>(kcache, vcache, cpos, pkhf, pvhf);
    splitA_all_kernel<<<3072, 256>>>(Wq, Wk, Wv, Wo, pWqkv, pWo);
    transpose_splitB_kernel<<<dim3(Q_/32, HID_/32), dim3(32,8)>>>(hidden, pHid);

    cudaFuncSetAttribute(gemm_pk_kernel, cudaFuncAttributeMaxDynamicSharedMemorySize, GEMM_SMEM);
    // fused QKV projection (M=4096)
    gemm_pk_kernel<<<dim3(8,32,1), 256, GEMM_SMEM>>>(pWqkv, pHid, bq, bk, bv, pqkv);

    rope_all_kernel<<<dim3(Q_/32, 32), dim3(32,8)>>>(pqkv, cosQD, sinQD, cpos, pqh, pkhf, pvhf);

    const int ATTN_SMEM = 5*64*136*2;   // 87040 B
    cudaFuncSetAttribute(attn_kernel, cudaFuncAttributeMaxDynamicSharedMemorySize, ATTN_SMEM);
    attn_kernel<<<dim3(Q_/64, H_), 128, ATTN_SMEM>>>(pqh, pkhf, pvhf, cpos, pAtt);

    // output projection: split-K=2 into g_qkv partials, then reduce
    gemm_pk_kernel<<<dim3(8,16,2), 256, GEMM_SMEM>>>(pWo, pAtt, nullptr, nullptr, nullptr, pqkv);
    addk_kernel<<<(HID_*Q_/4)/256, 256>>>(pqkv, out);
}